// round 4
// baseline (speedup 1.0000x reference)
#include <cuda_runtime.h>

typedef unsigned long long u64;
typedef unsigned int u32;

#define B_ 2048
#define I_ 512
#define O_ 256
#define NK (I_ / 2)     // 256 i-pairs
#define BM 16           // batch rows per block tile
#define OT 32           // output cols per block tile
#define RING 16         // slabs resident per ring
#define KG 4            // slabs per cp.async commit group

// wP[k][o]  = (w[2k][o], w[2k+1][o])           packed f32x2   (512KB)
// aT[k][b]  = (x[b][2k]*z[2k]-1, x[b][2k+1]*z[2k+1]-1)        (4MB)
__device__ u64 wP_g[NK * O_];
__device__ u64 aT_g[NK * B_];

__device__ __forceinline__ u64 fma2_(u64 a, u64 b, u64 c) {
    u64 d;
    asm("fma.rn.f32x2 %0, %1, %2, %3;" : "=l"(d) : "l"(a), "l"(b), "l"(c));
    return d;
}
__device__ __forceinline__ u64 mul2_(u64 a, u64 b) {
    u64 d;
    asm("mul.rn.f32x2 %0, %1, %2;" : "=l"(d) : "l"(a), "l"(b));
    return d;
}
__device__ __forceinline__ void cpa16(u32 saddr, const void* g) {
    asm volatile("cp.async.cg.shared.global [%0], [%1], 16;" :: "r"(saddr), "l"(g));
}
__device__ __forceinline__ void cpa_commit() { asm volatile("cp.async.commit_group;"); }
__device__ __forceinline__ void cpa_wait3()  { asm volatile("cp.async.wait_group 3;"); }

// ---------------- K1: pack w into i-pair lanes ----------------
__global__ void pack_w_kernel(const float* __restrict__ w) {
    int k = blockIdx.x;   // 0..NK-1
    int o = threadIdx.x;  // 0..O_-1
    float lo = w[(2 * k) * O_ + o];
    float hi = w[(2 * k + 1) * O_ + o];
    u64 v;
    asm("mov.b64 %0, {%1, %2};" : "=l"(v) : "f"(lo), "f"(hi));
    wP_g[k * O_ + o] = v;
}

// ---------------- K2: a = x*z-1, transposed to [k][b] ----------------
#define KT 32   // k-pairs per block
#define BT 64   // batch rows per block
__global__ __launch_bounds__(256) void transpose_a_kernel(
    const float* __restrict__ x, const float* __restrict__ qz)
{
    __shared__ __align__(16) u64 buf[KT][BT + 1];  // +1 u64 pad: conflict-free transpose
    __shared__ float zsh[2 * KT];

    const int tid = threadIdx.x;
    const int k0 = (blockIdx.x & 7) * KT;
    const int b0 = (blockIdx.x >> 3) * BT;

    if (tid < 2 * KT) {
        float q = qz[2 * k0 + tid];
        float pi = 1.0f / (1.0f + expf(-q));
        zsh[tid] = fminf(fmaxf(fmaf(pi, 1.2f, -0.1f), 0.0f), 1.0f);
    }
    __syncthreads();

    const u64 neg2 = 0xBF800000BF800000ULL;
    const u64* zd = (const u64*)zsh;
    // phase 1: coalesced x reads (256B per row-pass), strided smem writes (pad-safe)
    const int kp = tid & (KT - 1);
    const int br = tid >> 5;   // 8 rows per pass
#pragma unroll
    for (int p = 0; p < BT / 8; ++p) {
        int b = p * 8 + br;
        u64 x2 = *(const u64*)(x + (b0 + b) * I_ + 2 * (k0 + kp));
        buf[kp][b] = fma2_(x2, zd[kp], neg2);
    }
    __syncthreads();
    // phase 2: coalesced global writes (warp = 32 consecutive b for one kp)
#pragma unroll
    for (int j = 0; j < (KT * BT) / 256; ++j) {
        int idx = tid + 256 * j;
        int kq = idx >> 6;
        int b = idx & (BT - 1);
        aT_g[(k0 + kq) * B_ + b0 + b] = buf[kq][b];
    }
}

// ---------------- K3: main ----------------
__global__ __launch_bounds__(32, 16) void l0conj_main(float* __restrict__ out)
{
    __shared__ __align__(16) u64 wring[RING * OT];  // 4KB
    __shared__ __align__(16) u64 aring[RING * BM];  // 2KB

    const int tid = threadIdx.x;
    const int b0 = (blockIdx.x >> 3) * BM;
    const int os = (blockIdx.x & 7) * OT;

    const u32 wsm = (u32)__cvta_generic_to_shared(wring);
    const u32 asm_ = (u32)__cvta_generic_to_shared(aring);

    // Per-slab copy jobs (one cp.async.16 per participating thread):
    //  threads 0..15  : w slab (32 u64 = 16 x 16B)
    //  threads 16..23 : a slab (16 u64 = 8 x 16B)
    const bool isW = tid < 16;
    const bool isA = (tid >= 16) & (tid < 24);
    const int t2 = isW ? tid * 2 : (tid - 16) * 2;

#define PREF(ks, slot)                                                         \
    {                                                                          \
        if (isW) cpa16(wsm + (u32)(((slot) * OT + t2) * 8),                    \
                       wP_g + (ks) * O_ + os + t2);                            \
        else if (isA) cpa16(asm_ + (u32)(((slot) * BM + t2) * 8),              \
                            aT_g + (ks) * B_ + b0 + t2);                       \
    }

    // Fill the ring.
#pragma unroll
    for (int g = 0; g < RING / KG; ++g) {
#pragma unroll
        for (int u = 0; u < KG; ++u) PREF(g * KG + u, g * KG + u);
        cpa_commit();
    }

    // Thread tile: 4 batch rows x 4 o's; lanes hold (even-i, odd-i) partial products.
    const int oth = (tid & 7) * 4;   // o offset within tile
    const int bth = (tid >> 3) * 4;  // b offset within tile

    const u64 one2 = 0x3F8000003F800000ULL;
    u64 p[4][4];
#pragma unroll
    for (int r = 0; r < 4; ++r)
#pragma unroll
        for (int c = 0; c < 4; ++c) p[r][c] = one2;

    const u64* wB = wring + oth;
    const u64* aB = aring + bth;

    int kpref = RING;
#pragma unroll 1
    for (int kb = 0; kb < NK; kb += KG) {
        cpa_wait3();
        __syncwarp();

#pragma unroll
        for (int u = 0; u < KG; ++u) {
            const int slot = (kb + u) & (RING - 1);
            ulonglong2 a01 = *(const ulonglong2*)(aB + slot * BM);      // rows bth,bth+1
            ulonglong2 a23 = *(const ulonglong2*)(aB + slot * BM + 2);  // rows bth+2,bth+3
            ulonglong2 w01 = *(const ulonglong2*)(wB + slot * OT);      // o,o+1
            ulonglong2 w23 = *(const ulonglong2*)(wB + slot * OT + 2);  // o+2,o+3
            u64 av[4] = {a01.x, a01.y, a23.x, a23.y};
            u64 wv[4] = {w01.x, w01.y, w23.x, w23.y};
#pragma unroll
            for (int r = 0; r < 4; ++r)
#pragma unroll
                for (int c = 0; c < 4; ++c)
                    p[r][c] = mul2_(p[r][c], fma2_(av[r], wv[c], one2));
        }

        // Keep 3 groups in flight (tail wraps; redundant fetches are harmless).
#pragma unroll
        for (int u = 0; u < KG; ++u) {
            int ks = (kpref + u) & (NK - 1);
            PREF(ks, (kpref + u) & (RING - 1));
        }
        cpa_commit();
        kpref += KG;
    }

    // Epilogue: scalar out = lane0 * lane1.
#pragma unroll
    for (int r = 0; r < 4; ++r) {
        float4 v;
        float lo, hi;
        asm("mov.b64 {%0, %1}, %2;" : "=f"(lo), "=f"(hi) : "l"(p[r][0])); v.x = lo * hi;
        asm("mov.b64 {%0, %1}, %2;" : "=f"(lo), "=f"(hi) : "l"(p[r][1])); v.y = lo * hi;
        asm("mov.b64 {%0, %1}, %2;" : "=f"(lo), "=f"(hi) : "l"(p[r][2])); v.z = lo * hi;
        asm("mov.b64 {%0, %1}, %2;" : "=f"(lo), "=f"(hi) : "l"(p[r][3])); v.w = lo * hi;
        *(float4*)(out + (b0 + bth + r) * O_ + os + oth) = v;
    }
}

extern "C" void kernel_launch(void* const* d_in, const int* in_sizes, int n_in,
                              void* d_out, int out_size) {
    const float* x = nullptr;
    const float* w = nullptr;
    const float* qz = nullptr;
    for (int i = 0; i < n_in; ++i) {
        if (in_sizes[i] == B_ * I_)      x  = (const float*)d_in[i];
        else if (in_sizes[i] == I_ * O_) w  = (const float*)d_in[i];
        else if (in_sizes[i] == I_)      qz = (const float*)d_in[i];
    }
    pack_w_kernel<<<NK, O_>>>(w);
    transpose_a_kernel<<<(NK / KT) * (B_ / BT), 256>>>(x, qz);
    l0conj_main<<<(B_ / BM) * (O_ / OT), 32>>>((float*)d_out);
}

// round 6
// speedup vs baseline: 1.5246x; 1.5246x over previous
#include <cuda_runtime.h>

typedef unsigned long long u64;
typedef unsigned int u32;

#define B_ 2048
#define I_ 512
#define O_ 256
#define BM 16            // batch rows per block
#define OT 128           // output cols per block
#define KSPL 4           // split-K factor
#define IB (I_ / KSPL)   // 128 i's per block
#define NTH 64
#define KG 4             // i's per cp.async commit group
#define NG (IB / KG)     // 32 groups
#define RG 8             // ring capacity in groups (16KB)
#define PF 6             // groups committed ahead (distance 5 after wait)

// Split-K partial products: part_g[ks][b][o]
__device__ float part_g[KSPL * B_ * O_];

__device__ __forceinline__ u64 fma2_(u64 a, u64 b, u64 c) {
    u64 d;
    asm("fma.rn.f32x2 %0, %1, %2, %3;" : "=l"(d) : "l"(a), "l"(b), "l"(c));
    return d;
}
__device__ __forceinline__ u64 mul2_(u64 a, u64 b) {
    u64 d;
    asm("mul.rn.f32x2 %0, %1, %2;" : "=l"(d) : "l"(a), "l"(b));
    return d;
}
__device__ __forceinline__ u64 dup2_(float a) {
    u64 d;
    asm("mov.b64 %0, {%1, %1};" : "=l"(d) : "f"(a));
    return d;
}
__device__ __forceinline__ void cpa16(u32 saddr, const void* g) {
    asm volatile("cp.async.cg.shared.global [%0], [%1], 16;" :: "r"(saddr), "l"(g));
}
__device__ __forceinline__ void cpa_commit() { asm volatile("cp.async.commit_group;"); }
__device__ __forceinline__ void cpa_wait5()  { asm volatile("cp.async.wait_group 5;"); }

// ---------------- main: one block = (ks, b-tile, o-half) ----------------
__global__ __launch_bounds__(NTH) void l0conj_main(
    const float* __restrict__ x,      // [B_, I_]
    const float* __restrict__ w,      // [I_, O_]
    const float* __restrict__ qz)     // [I_]
{
    __shared__ __align__(16) float zsm[IB];              // 512B
    __shared__ __align__(16) float aP[IB * BM];          // 8KB  aP[i][b] = x[b][i]*z[i]-1
    __shared__ __align__(16) float wring[RG * KG * OT];  // 16KB

    const int tid = threadIdx.x;
    const int ks = blockIdx.x & (KSPL - 1);
    const int ot = (blockIdx.x >> 2) & 1;
    const int bt = blockIdx.x >> 3;
    const int i0 = ks * IB;
    const int os = ot * OT;
    const int b0 = bt * BM;

    const u32 wsm = (u32)__cvta_generic_to_shared(wring);
    const float* wg = w + i0 * O_ + os;   // + i*O_ + col

    // Prefetch one group = KG slabs (KG*OT f32 = 2KB = 128 x 16B chunks);
    // thread copies chunks tid and tid+64.
#define PREFW(gsrc, gslot)                                                   \
    {                                                                        \
        _Pragma("unroll") for (int h = 0; h < 2; ++h) {                      \
            int c = tid + 64 * h;                                            \
            int s = c >> 5;                                                  \
            int off = c & 31;                                                \
            cpa16(wsm + (u32)((((gslot) * KG + s) * OT + off * 4) * 4),      \
                  wg + ((gsrc) * KG + s) * O_ + off * 4);                    \
        }                                                                    \
        cpa_commit();                                                        \
    }

    // Fill PF groups up front so L2 latency overlaps the prologue.
#pragma unroll
    for (int g = 0; g < PF; ++g) PREFW(g, g);

    // z for this block's i-range
    {
        float q0 = qz[i0 + 2 * tid];
        float q1 = qz[i0 + 2 * tid + 1];
        float p0 = 1.0f / (1.0f + expf(-q0));
        float p1 = 1.0f / (1.0f + expf(-q1));
        zsm[2 * tid]     = fminf(fmaxf(fmaf(p0, 1.2f, -0.1f), 0.0f), 1.0f);
        zsm[2 * tid + 1] = fminf(fmaxf(fmaf(p1, 1.2f, -0.1f), 0.0f), 1.0f);
    }
    __syncthreads();

    // a = x*z - 1 into aP[i][b]. Thread: row r = tid&15, i-chunk ic = tid>>4 (32 i's).
    {
        const int r = tid & 15;
        const int ic = tid >> 4;
        const float* xrow = x + (b0 + r) * I_ + i0 + ic * 32;
        const float* zc = zsm + ic * 32;
        float* ac = aP + ic * 32 * BM + r;
#pragma unroll
        for (int j4 = 0; j4 < 8; ++j4) {
            float4 xv = *(const float4*)(xrow + j4 * 4);
            float4 zv = *(const float4*)(zc + j4 * 4);
            ac[(j4 * 4 + 0) * BM] = fmaf(xv.x, zv.x, -1.0f);
            ac[(j4 * 4 + 1) * BM] = fmaf(xv.y, zv.y, -1.0f);
            ac[(j4 * 4 + 2) * BM] = fmaf(xv.z, zv.z, -1.0f);
            ac[(j4 * 4 + 3) * BM] = fmaf(xv.w, zv.w, -1.0f);
        }
    }
    __syncthreads();

    // Thread tile: 4 batch rows x 8 o's (4 o-pair accumulator columns).
    const int og = tid & 15;          // o-offset = og*8
    const int bth = (tid >> 4) * 4;   // rows bth..bth+3

    const u64 one2 = 0x3F8000003F800000ULL;
    u64 p[4][4];
#pragma unroll
    for (int r = 0; r < 4; ++r)
#pragma unroll
        for (int c = 0; c < 4; ++c) p[r][c] = one2;

    const float* aB = aP + bth;
    const float* wB = wring + og * 8;

#pragma unroll 1
    for (int g = 0; g < NG; ++g) {
        // Race-free protocol:
        //   wait_group 5  -> this thread's commits through group g have landed
        //   __syncthreads -> everyone waited => ALL copies of group g visible;
        //                    also: all threads finished compute through g-1.
        // Prefetch target slot (g+PF)&7 last held group g-2 (<= g-1): nobody
        // can still be reading it after the barrier.
        cpa_wait5();
        __syncthreads();

        const int gslot = g & (RG - 1);
#pragma unroll
        for (int u = 0; u < KG; ++u) {
            const int i = g * KG + u;
            float4 av = *(const float4*)(aB + i * BM);            // rows bth..bth+3
            const float* ws = wB + (gslot * KG + u) * OT;
            ulonglong2 w01 = *(const ulonglong2*)(ws);            // (o,o+1),(o+2,o+3)
            ulonglong2 w23 = *(const ulonglong2*)(ws + 4);        // (o+4..o+7)
            u64 ad[4] = {dup2_(av.x), dup2_(av.y), dup2_(av.z), dup2_(av.w)};
            u64 wv[4] = {w01.x, w01.y, w23.x, w23.y};
#pragma unroll
            for (int r = 0; r < 4; ++r)
#pragma unroll
                for (int c = 0; c < 4; ++c)
                    p[r][c] = mul2_(p[r][c], fma2_(ad[r], wv[c], one2));
        }

        PREFW((g + PF) & (NG - 1), (g + PF) & (RG - 1));  // tail wraps: fetched, never used
    }

    // Partial product out: part_g[ks][b][o..o+7]
    float* pg = part_g + ks * (B_ * O_) + (b0 + bth) * O_ + os + og * 8;
#pragma unroll
    for (int r = 0; r < 4; ++r) {
        *(ulonglong2*)(pg + r * O_)     = make_ulonglong2(p[r][0], p[r][1]);
        *(ulonglong2*)(pg + r * O_ + 4) = make_ulonglong2(p[r][2], p[r][3]);
    }
}

// ---------------- combine: out = prod of 4 partials ----------------
__global__ __launch_bounds__(256) void l0conj_combine(float* __restrict__ out)
{
    int t = blockIdx.x * 256 + threadIdx.x;   // over B_*O_/4 float4s
    const float4* p0 = (const float4*)part_g;
    const float4* p1 = p0 + (B_ * O_ / 4);
    const float4* p2 = p1 + (B_ * O_ / 4);
    const float4* p3 = p2 + (B_ * O_ / 4);
    float4 a = p0[t], b = p1[t], c = p2[t], d = p3[t];
    float4 r;
    r.x = a.x * b.x * c.x * d.x;
    r.y = a.y * b.y * c.y * d.y;
    r.z = a.z * b.z * c.z * d.z;
    r.w = a.w * b.w * c.w * d.w;
    ((float4*)out)[t] = r;
}

extern "C" void kernel_launch(void* const* d_in, const int* in_sizes, int n_in,
                              void* d_out, int out_size) {
    const float* x = nullptr;
    const float* w = nullptr;
    const float* qz = nullptr;
    for (int i = 0; i < n_in; ++i) {
        if (in_sizes[i] == B_ * I_)      x  = (const float*)d_in[i];
        else if (in_sizes[i] == I_ * O_) w  = (const float*)d_in[i];
        else if (in_sizes[i] == I_)      qz = (const float*)d_in[i];
    }
    l0conj_main<<<KSPL * (B_ / BM) * (O_ / OT), NTH>>>(x, w, qz);
    l0conj_combine<<<(B_ * O_ / 4) / 256, 256>>>((float*)d_out);
}